// round 3
// baseline (speedup 1.0000x reference)
#include <cuda_runtime.h>
#include <cstdint>
#include <cstddef>

// ============================================================================
// RNN_4715874091371 — GB300 sm_103a (compiled via compute_103: tcgen05 is
// unavailable; tensor path = mma.sync m16n8k8 tf32)
//   Z = X @ W_ih^T + (b_ih + b_hh)             one big GEMM (65536x1024x1024)
//   h_0 = tanh(Z_0);  h_t = tanh(Z_t + h_{t-1} @ W_hh^T)       63 step GEMMs
//   p = sigmoid(h @ W_out^T + b_out);  loss = BCE(p, y >= 1e-5)
// W matrices RN-rounded to tf32 once; h RN-rounded at epilogue; fp32 accum.
// ============================================================================

static constexpr int TT = 64;
static constexpr int BB = 1024;
static constexpr int HH = 1024;

// ---------------- device scratch (allocation-free rule) --------------------
__device__ float g_Wih[(size_t)HH * HH];
__device__ float g_Whh[(size_t)HH * HH];
__device__ float g_Z[(size_t)TT * BB * HH];      // [t][b][h]
__device__ float g_h[2][(size_t)BB * HH];        // ping-pong hidden state
__device__ float g_p[BB];

#define DEVI __device__ __forceinline__

DEVI uint32_t smem_u32(const void* p) {
    uint32_t a;
    asm("{ .reg .u64 t; cvta.to.shared.u64 t, %1; cvt.u32.u64 %0, t; }"
        : "=r"(a) : "l"(p));
    return a;
}
DEVI float tf32_rn(float x) {                    // round-to-nearest tf32
    uint32_t u;
    asm("cvt.rna.tf32.f32 %0, %1;" : "=r"(u) : "f"(x));
    return __uint_as_float(u);
}

#define CPA16(dst_b, src) \
    asm volatile("cp.async.cg.shared.global [%0], [%1], 16;" :: "r"(dst_b), "l"(src))
#define CPC()    asm volatile("cp.async.commit_group;" ::: "memory")
#define CPW2()   asm volatile("cp.async.wait_group 2;" ::: "memory")

// D += A * B   (m16n8k8, tf32 in, f32 accum)
#define MMA8(d, a, b)                                                           \
    asm("mma.sync.aligned.m16n8k8.row.col.f32.tf32.tf32.f32 "                   \
        "{%0,%1,%2,%3}, {%4,%5,%6,%7}, {%8,%9}, {%0,%1,%2,%3};"                 \
        : "+f"((d)[0]), "+f"((d)[1]), "+f"((d)[2]), "+f"((d)[3])                \
        : "r"((a)[0]), "r"((a)[1]), "r"((a)[2]), "r"((a)[3]),                   \
          "r"((b)[0]), "r"((b)[1]))

// ------------------------------- GEMM kernel -------------------------------
// C[MT,128] = A[MT,1024] @ W[128 rows,1024]^T  (tf32 mma.sync, fp32 accum)
//   STEP=false: A=Aext(av), W=g_Wih; epi: v+bih[n]+bhh[n] -> g_Z[t][b][n]
//   STEP=true : A=g_h[hsrc], W=g_Whh; epi: rn(tanh(v+Z_t[r][n])) -> g_h[hdst]
// smem: 4 stages of (A: MT x 32 | B: 128 x 32) floats, row stride 36 (pad)
template <int MT, bool STEP>
__global__ __launch_bounds__(256, 1)
void gemm_k(const float* __restrict__ Aext,
            const float* __restrict__ bih, const float* __restrict__ bhh,
            int t, int hsrc, int hdst)
{
    constexpr int WGM   = (MT == 128) ? 2 : 1;   // warp grid (M x N), 8 warps
    constexpr int WGN   = 8 / WGM;
    constexpr int WM    = MT / WGM;              // 64
    constexpr int WN    = 128 / WGN;             // 32 or 16
    constexpr int MFRAG = WM / 16;               // 4
    constexpr int NFRAG = WN / 8;                // 4 or 2
    constexpr int SASZ  = MT * 36;               // floats per A stage
    constexpr int SBSZ  = 128 * 36;
    constexpr int STG   = SASZ + SBSZ;
    constexpr int NCH   = 32;                    // K chunks of 32 floats

    extern __shared__ __align__(16) float sm[];
    const uint32_t smb = smem_u32(sm);

    const int tid  = threadIdx.x;
    const int lane = tid & 31;
    const int wid  = tid >> 5;
    const int wm   = wid / WGN;
    const int wn   = wid % WGN;
    const int m0   = blockIdx.x * MT;
    const int n0   = blockIdx.y * 128;

    const float* __restrict__ A = STEP ? g_h[hsrc] : Aext;
    const float* __restrict__ W = STEP ? g_Whh : g_Wih;
    const float* __restrict__ Zt = STEP ? (g_Z + (size_t)t * BB * HH) : nullptr;
    float* __restrict__ out = STEP ? g_h[hdst] : g_Z;

    // ---- stage loader: chunk c -> slot s ----
    auto load_stage = [&](int c, int s) {
        const int kf = c * 32;
        const uint32_t ab = smb + (uint32_t)(s * STG) * 4;
        const uint32_t bb = ab + (uint32_t)SASZ * 4;
        #pragma unroll
        for (int i = 0; i < MT * 8 / 256; ++i) {            // A: MT rows x 128B
            int e = tid + i * 256, r = e >> 3, j = e & 7;
            CPA16(ab + (uint32_t)(r * 36 + j * 4) * 4,
                  A + (size_t)(m0 + r) * HH + kf + j * 4);
        }
        #pragma unroll
        for (int i = 0; i < 4; ++i) {                       // B: 128 rows x 128B
            int e = tid + i * 256, r = e >> 3, j = e & 7;
            CPA16(bb + (uint32_t)(r * 36 + j * 4) * 4,
                  W + (size_t)(n0 + r) * HH + kf + j * 4);
        }
    };

    // prologue: stages 0..2
    #pragma unroll
    for (int c = 0; c < 3; ++c) { load_stage(c, c); CPC(); }

    float acc[MFRAG][NFRAG][4];
    #pragma unroll
    for (int mi = 0; mi < MFRAG; ++mi)
        #pragma unroll
        for (int nf = 0; nf < NFRAG; ++nf)
            #pragma unroll
            for (int j = 0; j < 4; ++j) acc[mi][nf][j] = 0.f;

    const int arow = wm * WM + (lane >> 2);
    const int bcol0 = lane & 3;

    for (int c = 0; c < NCH; ++c) {
        CPW2();                    // chunk c landed (<=2 groups pending)
        __syncthreads();
        if (c + 3 < NCH) load_stage(c + 3, (c + 3) & 3);
        CPC();

        const float* sA = sm + (c & 3) * STG;
        const float* sB = sA + SASZ;

        #pragma unroll
        for (int ks = 0; ks < 4; ++ks) {
            const int col = ks * 8 + bcol0;
            uint32_t a[MFRAG][4];
            #pragma unroll
            for (int mi = 0; mi < MFRAG; ++mi) {
                const float* p = sA + (arow + mi * 16) * 36 + col;
                a[mi][0] = __float_as_uint(p[0]);
                a[mi][1] = __float_as_uint(p[8 * 36]);
                a[mi][2] = __float_as_uint(p[4]);
                a[mi][3] = __float_as_uint(p[8 * 36 + 4]);
            }
            uint32_t b[NFRAG][2];
            #pragma unroll
            for (int nf = 0; nf < NFRAG; ++nf) {
                const float* p = sB + (wn * WN + nf * 8 + (lane >> 2)) * 36 + col;
                b[nf][0] = __float_as_uint(p[0]);
                b[nf][1] = __float_as_uint(p[4]);
            }
            #pragma unroll
            for (int mi = 0; mi < MFRAG; ++mi)
                #pragma unroll
                for (int nf = 0; nf < NFRAG; ++nf)
                    MMA8(acc[mi][nf], a[mi], b[nf]);
        }
        __syncthreads();           // compute(c) done before slot c&3 is refilled
    }

    // ------------------------------ epilogue --------------------------------
    #pragma unroll
    for (int mi = 0; mi < MFRAG; ++mi) {
        const int r0 = m0 + wm * WM + mi * 16 + (lane >> 2);
        #pragma unroll
        for (int nf = 0; nf < NFRAG; ++nf) {
            const int cg = n0 + wn * WN + nf * 8 + (lane & 3) * 2;
            #pragma unroll
            for (int half = 0; half < 2; ++half) {
                const int r = r0 + half * 8;
                const float v0 = acc[mi][nf][half * 2 + 0];
                const float v1 = acc[mi][nf][half * 2 + 1];
                if (STEP) {
                    const float2 z = *(const float2*)(Zt + (size_t)r * HH + cg);
                    float2 o;
                    o.x = tf32_rn(tanhf(v0 + z.x));
                    o.y = tf32_rn(tanhf(v1 + z.y));
                    *(float2*)(out + (size_t)r * HH + cg) = o;
                } else {
                    float2 o;
                    o.x = v0 + bih[cg] + bhh[cg];
                    o.y = v1 + bih[cg + 1] + bhh[cg + 1];
                    const int b = r >> 6, tt = r & 63;   // av row = b*T + t
                    *(float2*)(out + ((size_t)tt * BB + b) * HH + cg) = o;
                }
            }
        }
    }
}

// ----------------------------- small kernels --------------------------------
__global__ void round_W_k(const float4* __restrict__ wih,
                          const float4* __restrict__ whh, int n4) {
    int i = blockIdx.x * blockDim.x + threadIdx.x;
    if (i < n4) {
        float4 a = wih[i], b = whh[i];
        a.x = tf32_rn(a.x); a.y = tf32_rn(a.y); a.z = tf32_rn(a.z); a.w = tf32_rn(a.w);
        b.x = tf32_rn(b.x); b.y = tf32_rn(b.y); b.z = tf32_rn(b.z); b.w = tf32_rn(b.w);
        ((float4*)g_Wih)[i] = a;
        ((float4*)g_Whh)[i] = b;
    }
}

__global__ void init_h_k() {                      // h0 = tanh(Z_0)
    int i = blockIdx.x * blockDim.x + threadIdx.x;
    g_h[0][i] = tf32_rn(tanhf(g_Z[i]));
}

__global__ void head_k(const float* __restrict__ Wout,
                       const float* __restrict__ bout) {
    int wid = threadIdx.x >> 5, lane = threadIdx.x & 31;
    int row = blockIdx.x * 8 + wid;               // 128 blocks x 8 warps
    const float4* hr = (const float4*)(g_h[1] + (size_t)row * HH);
    const float4* wr = (const float4*)Wout;
    float s = 0.f;
    for (int i = lane; i < HH / 4; i += 32) {
        float4 a = hr[i], b = wr[i];
        s += a.x * b.x + a.y * b.y + a.z * b.z + a.w * b.w;
    }
    #pragma unroll
    for (int o = 16; o; o >>= 1) s += __shfl_xor_sync(0xFFFFFFFFu, s, o);
    if (lane == 0) g_p[row] = 1.f / (1.f + expf(-(s + bout[0])));
}

__global__ void loss_k(const float* __restrict__ y, float* __restrict__ out,
                       int out_size) {
    __shared__ float red[32];
    int tid = threadIdx.x;                        // 1024 threads
    float pv = g_p[tid];
    float yb = (y[tid] >= 1e-5f) ? 1.f : 0.f;
    float term = yb * fmaxf(logf(pv), -100.f)
               + (1.f - yb) * fmaxf(log1pf(-pv), -100.f);
    #pragma unroll
    for (int o = 16; o; o >>= 1) term += __shfl_xor_sync(0xFFFFFFFFu, term, o);
    if ((tid & 31) == 0) red[tid >> 5] = term;
    __syncthreads();
    if (tid < 32) {
        float v = red[tid];
        #pragma unroll
        for (int o = 16; o; o >>= 1) v += __shfl_xor_sync(0xFFFFFFFFu, v, o);
        if (tid == 0 && out_size != BB) out[0] = -v / (float)BB;
    }
    if (out_size >= 1 + BB)      out[1 + tid] = pv;
    else if (out_size == BB)     out[tid] = pv;
    for (int i = 1 + BB + tid; i < out_size; i += BB) out[i] = 0.f;
}

// ------------------------------- launcher -----------------------------------
extern "C" void kernel_launch(void* const* d_in, const int* in_sizes, int n_in,
                              void* d_out, int out_size) {
    const float* av   = (const float*)d_in[3];
    const float* y    = (const float*)d_in[4];
    const float* Wih  = (const float*)d_in[5];
    const float* bih  = (const float*)d_in[6];
    const float* Whh  = (const float*)d_in[7];
    const float* bhh  = (const float*)d_in[8];
    const float* Wout = (const float*)d_in[9];
    const float* bout = (const float*)d_in[10];
    (void)in_sizes; (void)n_in;

    constexpr int SMEM1 = 4 * (128 * 36 + 128 * 36) * 4;   // 147456 B
    constexpr int SMEM2 = 4 * (64 * 36 + 128 * 36) * 4;    // 110592 B
    cudaFuncSetAttribute(gemm_k<128, false>,
                         cudaFuncAttributeMaxDynamicSharedMemorySize, SMEM1);
    cudaFuncSetAttribute(gemm_k<64, true>,
                         cudaFuncAttributeMaxDynamicSharedMemorySize, SMEM2);

    // 1) RN-round weight matrices to tf32 (one pass)
    round_W_k<<<(HH * HH / 4 + 255) / 256, 256>>>(
        (const float4*)Wih, (const float4*)Whh, HH * HH / 4);

    // 2) Z = X @ W_ih^T + b_ih + b_hh   (65536 x 1024 x 1024)
    gemm_k<128, false><<<dim3(512, 8), 256, SMEM1>>>(av, bih, bhh, 0, 0, 0);

    // 3) h_0 = tanh(Z_0)
    init_h_k<<<BB * HH / 256, 256>>>();

    // 4) recurrence: h_t = tanh(Z_t + h_{t-1} @ W_hh^T)
    for (int t = 1; t < TT; ++t)
        gemm_k<64, true><<<dim3(16, 8), 256, SMEM2>>>(
            nullptr, nullptr, nullptr, t, (t - 1) & 1, t & 1);

    // 5) head + loss (final h in g_h[1])
    head_k<<<128, 256>>>(Wout, bout);
    loss_k<<<1, BB>>>(y, (float*)d_out, out_size);
}

// round 4
// speedup vs baseline: 1.2050x; 1.2050x over previous
#include <cuda_runtime.h>
#include <cstdint>
#include <cstddef>

// ============================================================================
// RNN_4715874091371 — GB300 sm_103a (compute_103 PTX: mma.sync tf32 path)
//   Z = X @ W_ih^T + (b_ih + b_hh)                 big GEMM (65536x1024x1024)
//   h_0 = tanh(Z_0); h_t = tanh(Z_t + h_{t-1} @ W_hh^T)   persistent kernel,
//                                                   63 steps, sw grid barrier
//   p = sigmoid(h @ W_out^T + b_out);  loss = BCE(p, y >= 1e-5)
// ============================================================================

static constexpr int TT = 64;
static constexpr int BB = 1024;
static constexpr int HH = 1024;
static constexpr int NSTEP_CTAS = 128;           // 16 m-tiles x 8 n-tiles

// ---------------- device scratch (allocation-free rule) --------------------
__device__ float g_Wih[(size_t)HH * HH];
__device__ float g_Whh[(size_t)HH * HH];
__device__ float g_Z[(size_t)TT * BB * HH];      // [t][b][h]
__device__ float g_h[2][(size_t)BB * HH];        // ping-pong hidden state
__device__ float g_p[BB];
__device__ unsigned g_bar;                        // grid barrier counter

#define DEVI __device__ __forceinline__

DEVI uint32_t smem_u32(const void* p) {
    uint32_t a;
    asm("{ .reg .u64 t; cvta.to.shared.u64 t, %1; cvt.u32.u64 %0, t; }"
        : "=r"(a) : "l"(p));
    return a;
}
DEVI float tf32_rn(float x) {
    uint32_t u;
    asm("cvt.rna.tf32.f32 %0, %1;" : "=r"(u) : "f"(x));
    return __uint_as_float(u);
}

#define CPA16(dst_b, src) \
    asm volatile("cp.async.cg.shared.global [%0], [%1], 16;" :: "r"(dst_b), "l"(src))
#define CPC()    asm volatile("cp.async.commit_group;" ::: "memory")
#define CPW2()   asm volatile("cp.async.wait_group 2;" ::: "memory")

// D += A * B   (m16n8k8, tf32 in, f32 accum)
#define MMA8(d, a, b)                                                           \
    asm("mma.sync.aligned.m16n8k8.row.col.f32.tf32.tf32.f32 "                   \
        "{%0,%1,%2,%3}, {%4,%5,%6,%7}, {%8,%9}, {%0,%1,%2,%3};"                 \
        : "+f"((d)[0]), "+f"((d)[1]), "+f"((d)[2]), "+f"((d)[3])                \
        : "r"((a)[0]), "r"((a)[1]), "r"((a)[2]), "r"((a)[3]),                   \
          "r"((b)[0]), "r"((b)[1]))

// ============================================================================
// Big GEMM: Z = X @ W_ih^T + (b_ih+b_hh).  Tile 128x128, 3 stages, 2 CTAs/SM.
// grid(x = 8 n-tiles  [fast], y = 512 m-tiles) -> wave A-window L2-resident.
// ============================================================================
__global__ __launch_bounds__(256, 2)
void gemm_big(const float* __restrict__ A,
              const float* __restrict__ bih, const float* __restrict__ bhh)
{
    constexpr int SASZ = 128 * 36, SBSZ = 128 * 36, STG = SASZ + SBSZ;
    extern __shared__ __align__(16) float sm[];
    const uint32_t smb = smem_u32(sm);

    const int tid  = threadIdx.x;
    const int lane = tid & 31;
    const int wid  = tid >> 5;
    const int wm   = wid >> 2;            // 2 x 4 warp grid; warp tile 64x32
    const int wn   = wid & 3;
    const int n0   = blockIdx.x * 128;
    const int m0   = blockIdx.y * 128;

    auto load_stage = [&](int c, int s) {
        const int kf = c * 32;
        const uint32_t ab = smb + (uint32_t)(s * STG) * 4;
        const uint32_t bb = ab + (uint32_t)SASZ * 4;
        #pragma unroll
        for (int i = 0; i < 4; ++i) {                    // A: 128 rows x 128B
            int e = tid + i * 256, r = e >> 3, j = e & 7;
            CPA16(ab + (uint32_t)(r * 36 + j * 4) * 4,
                  A + (size_t)(m0 + r) * HH + kf + j * 4);
        }
        #pragma unroll
        for (int i = 0; i < 4; ++i) {                    // B: 128 rows x 128B
            int e = tid + i * 256, r = e >> 3, j = e & 7;
            CPA16(bb + (uint32_t)(r * 36 + j * 4) * 4,
                  g_Wih + (size_t)(n0 + r) * HH + kf + j * 4);
        }
    };

    #pragma unroll
    for (int c = 0; c < 3; ++c) { load_stage(c, c); CPC(); }

    float acc[4][4][4];
    #pragma unroll
    for (int mi = 0; mi < 4; ++mi)
        #pragma unroll
        for (int nf = 0; nf < 4; ++nf)
            #pragma unroll
            for (int j = 0; j < 4; ++j) acc[mi][nf][j] = 0.f;

    const int arow  = wm * 64 + (lane >> 2);
    const int bcol0 = lane & 3;

    for (int c = 0; c < 32; ++c) {
        CPW2();
        __syncthreads();
        const float* sA = sm + (c % 3) * STG;
        const float* sB = sA + SASZ;
        #pragma unroll
        for (int ks = 0; ks < 4; ++ks) {
            const int col = ks * 8 + bcol0;
            uint32_t a[4][4];
            #pragma unroll
            for (int mi = 0; mi < 4; ++mi) {
                const float* p = sA + (arow + mi * 16) * 36 + col;
                a[mi][0] = __float_as_uint(p[0]);
                a[mi][1] = __float_as_uint(p[8 * 36]);
                a[mi][2] = __float_as_uint(p[4]);
                a[mi][3] = __float_as_uint(p[8 * 36 + 4]);
            }
            uint32_t b[4][2];
            #pragma unroll
            for (int nf = 0; nf < 4; ++nf) {
                const float* p = sB + (wn * 32 + nf * 8 + (lane >> 2)) * 36 + col;
                b[nf][0] = __float_as_uint(p[0]);
                b[nf][1] = __float_as_uint(p[4]);
            }
            #pragma unroll
            for (int mi = 0; mi < 4; ++mi)
                #pragma unroll
                for (int nf = 0; nf < 4; ++nf)
                    MMA8(acc[mi][nf], a[mi], b[nf]);
        }
        __syncthreads();                  // compute(c) done before refilling slot
        if (c + 3 < 32) load_stage(c + 3, c % 3);
        CPC();
    }

    // epilogue: + biases, scatter to g_Z[t][b][n]  (m = b*64 + t)
    #pragma unroll
    for (int mi = 0; mi < 4; ++mi) {
        const int r0 = m0 + wm * 64 + mi * 16 + (lane >> 2);
        #pragma unroll
        for (int nf = 0; nf < 4; ++nf) {
            const int cg = n0 + wn * 32 + nf * 8 + (lane & 3) * 2;
            const float bsum0 = bih[cg] + bhh[cg];
            const float bsum1 = bih[cg + 1] + bhh[cg + 1];
            #pragma unroll
            for (int half = 0; half < 2; ++half) {
                const int r = r0 + half * 8;
                float2 o;
                o.x = acc[mi][nf][half * 2 + 0] + bsum0;
                o.y = acc[mi][nf][half * 2 + 1] + bsum1;
                const int b = r >> 6, t = r & 63;
                *(float2*)(g_Z + ((size_t)t * BB + b) * HH + cg) = o;
            }
        }
    }
}

// ============================================================================
// Persistent step kernel: 128 CTAs (tile 64x128), software grid barrier.
//   t=0: h0 = tanh(Z_0) tile;  t=1..63: h_t = tanh(Z_t + h_{t-1} @ W_hh^T)
// A (=h) loaded via cp.async.cg (L1-bypassed -> coherent at L2).
// ============================================================================
__global__ __launch_bounds__(256, 1)
void steps_k()
{
    constexpr int MT = 64, NT = 128;
    constexpr int SASZ = MT * 36, SBSZ = NT * 36, STG = SASZ + SBSZ;
    extern __shared__ __align__(16) float sm[];
    const uint32_t smb = smem_u32(sm);

    const int tid  = threadIdx.x;
    const int lane = tid & 31;
    const int wid  = tid >> 5;            // 1 x 8 warp grid; warp tile 64x16
    const int m0   = (blockIdx.x >> 3) * MT;
    const int n0   = (blockIdx.x & 7) * NT;

    // ---- t = 0: h0 = tanh(Z_0) on this CTA's tile ----
    for (int e = tid; e < MT * NT; e += 256) {
        int r = e >> 7, c = e & 127;
        size_t idx = (size_t)(m0 + r) * HH + n0 + c;
        g_h[0][idx] = tf32_rn(tanhf(g_Z[idx]));
    }
    __syncthreads();
    if (tid == 0) { __threadfence(); atomicAdd(&g_bar, 1); }

    const int arow  = lane >> 2;
    const int bcol0 = lane & 3;

    for (int t = 1; t < TT; ++t) {
        const float* __restrict__ Asrc = g_h[(t - 1) & 1];
        float*       __restrict__ out  = g_h[t & 1];
        const float* __restrict__ Zt   = g_Z + (size_t)t * BB * HH;

        // Z prefetch (independent of h) — hide DRAM latency behind barrier
        float2 zf[4][2][2];
        #pragma unroll
        for (int mi = 0; mi < 4; ++mi)
            #pragma unroll
            for (int nf = 0; nf < 2; ++nf) {
                const int cg = n0 + wid * 16 + nf * 8 + (lane & 3) * 2;
                #pragma unroll
                for (int half = 0; half < 2; ++half) {
                    const int r = m0 + mi * 16 + (lane >> 2) + half * 8;
                    zf[mi][nf][half] = *(const float2*)(Zt + (size_t)r * HH + cg);
                }
            }

        // ---- grid barrier: wait until all wrote h_{t-1} ----
        if (tid == 0) {
            const unsigned tgt = (unsigned)NSTEP_CTAS * (unsigned)t;
            while (*(volatile unsigned*)&g_bar < tgt) __nanosleep(64);
            __threadfence();
        }
        __syncthreads();

        auto load_stage = [&](int c, int s) {
            const int kf = c * 32;
            const uint32_t ab = smb + (uint32_t)(s * STG) * 4;
            const uint32_t bb = ab + (uint32_t)SASZ * 4;
            #pragma unroll
            for (int i = 0; i < 2; ++i) {                // A: 64 rows x 128B
                int e = tid + i * 256, r = e >> 3, j = e & 7;
                CPA16(ab + (uint32_t)(r * 36 + j * 4) * 4,
                      Asrc + (size_t)(m0 + r) * HH + kf + j * 4);
            }
            #pragma unroll
            for (int i = 0; i < 4; ++i) {                // B: 128 rows x 128B
                int e = tid + i * 256, r = e >> 3, j = e & 7;
                CPA16(bb + (uint32_t)(r * 36 + j * 4) * 4,
                      g_Whh + (size_t)(n0 + r) * HH + kf + j * 4);
            }
        };

        #pragma unroll
        for (int c = 0; c < 3; ++c) { load_stage(c, c); CPC(); }

        float acc[4][2][4];
        #pragma unroll
        for (int mi = 0; mi < 4; ++mi)
            #pragma unroll
            for (int nf = 0; nf < 2; ++nf)
                #pragma unroll
                for (int j = 0; j < 4; ++j) acc[mi][nf][j] = 0.f;

        for (int c = 0; c < 32; ++c) {
            CPW2();
            __syncthreads();
            if (c + 3 < 32) load_stage(c + 3, (c + 3) & 3);
            CPC();
            const float* sA = sm + (c & 3) * STG;
            const float* sB = sA + SASZ;
            #pragma unroll
            for (int ks = 0; ks < 4; ++ks) {
                const int col = ks * 8 + bcol0;
                uint32_t a[4][4];
                #pragma unroll
                for (int mi = 0; mi < 4; ++mi) {
                    const float* p = sA + (arow + mi * 16) * 36 + col;
                    a[mi][0] = __float_as_uint(p[0]);
                    a[mi][1] = __float_as_uint(p[8 * 36]);
                    a[mi][2] = __float_as_uint(p[4]);
                    a[mi][3] = __float_as_uint(p[8 * 36 + 4]);
                }
                uint32_t b[2][2];
                #pragma unroll
                for (int nf = 0; nf < 2; ++nf) {
                    const float* p = sB + (wid * 16 + nf * 8 + (lane >> 2)) * 36 + col;
                    b[nf][0] = __float_as_uint(p[0]);
                    b[nf][1] = __float_as_uint(p[4]);
                }
                #pragma unroll
                for (int mi = 0; mi < 4; ++mi)
                    #pragma unroll
                    for (int nf = 0; nf < 2; ++nf)
                        MMA8(acc[mi][nf], a[mi], b[nf]);
            }
            __syncthreads();
        }

        // epilogue: tanh(acc + Z_t) -> h[t&1]
        #pragma unroll
        for (int mi = 0; mi < 4; ++mi) {
            #pragma unroll
            for (int nf = 0; nf < 2; ++nf) {
                const int cg = n0 + wid * 16 + nf * 8 + (lane & 3) * 2;
                #pragma unroll
                for (int half = 0; half < 2; ++half) {
                    const int r = m0 + mi * 16 + (lane >> 2) + half * 8;
                    float2 o;
                    o.x = tf32_rn(tanhf(acc[mi][nf][half * 2 + 0] + zf[mi][nf][half].x));
                    o.y = tf32_rn(tanhf(acc[mi][nf][half * 2 + 1] + zf[mi][nf][half].y));
                    *(float2*)(out + (size_t)r * HH + cg) = o;
                }
            }
        }
        __syncthreads();
        if (tid == 0) { __threadfence(); atomicAdd(&g_bar, 1); }
    }
}

// ----------------------------- small kernels --------------------------------
__global__ void round_W_k(const float4* __restrict__ wih,
                          const float4* __restrict__ whh, int n4) {
    int i = blockIdx.x * blockDim.x + threadIdx.x;
    if (i == 0) g_bar = 0;                        // reset grid barrier (replays)
    if (i < n4) {
        float4 a = wih[i], b = whh[i];
        a.x = tf32_rn(a.x); a.y = tf32_rn(a.y); a.z = tf32_rn(a.z); a.w = tf32_rn(a.w);
        b.x = tf32_rn(b.x); b.y = tf32_rn(b.y); b.z = tf32_rn(b.z); b.w = tf32_rn(b.w);
        ((float4*)g_Wih)[i] = a;
        ((float4*)g_Whh)[i] = b;
    }
}

__global__ void head_k(const float* __restrict__ Wout,
                       const float* __restrict__ bout) {
    int wid = threadIdx.x >> 5, lane = threadIdx.x & 31;
    int row = blockIdx.x * 8 + wid;
    const float4* hr = (const float4*)(g_h[1] + (size_t)row * HH);
    const float4* wr = (const float4*)Wout;
    float s = 0.f;
    for (int i = lane; i < HH / 4; i += 32) {
        float4 a = hr[i], b = wr[i];
        s += a.x * b.x + a.y * b.y + a.z * b.z + a.w * b.w;
    }
    #pragma unroll
    for (int o = 16; o; o >>= 1) s += __shfl_xor_sync(0xFFFFFFFFu, s, o);
    if (lane == 0) g_p[row] = 1.f / (1.f + expf(-(s + bout[0])));
}

__global__ void loss_k(const float* __restrict__ y, float* __restrict__ out,
                       int out_size) {
    __shared__ float red[32];
    int tid = threadIdx.x;                        // 1024 threads
    float pv = g_p[tid];
    float yb = (y[tid] >= 1e-5f) ? 1.f : 0.f;
    float term = yb * fmaxf(logf(pv), -100.f)
               + (1.f - yb) * fmaxf(log1pf(-pv), -100.f);
    #pragma unroll
    for (int o = 16; o; o >>= 1) term += __shfl_xor_sync(0xFFFFFFFFu, term, o);
    if ((tid & 31) == 0) red[tid >> 5] = term;
    __syncthreads();
    if (tid < 32) {
        float v = red[tid];
        #pragma unroll
        for (int o = 16; o; o >>= 1) v += __shfl_xor_sync(0xFFFFFFFFu, v, o);
        if (tid == 0 && out_size != BB) out[0] = -v / (float)BB;
    }
    if (out_size >= 1 + BB)      out[1 + tid] = pv;
    else if (out_size == BB)     out[tid] = pv;
    for (int i = 1 + BB + tid; i < out_size; i += BB) out[i] = 0.f;
}

// ------------------------------- launcher -----------------------------------
extern "C" void kernel_launch(void* const* d_in, const int* in_sizes, int n_in,
                              void* d_out, int out_size) {
    const float* av   = (const float*)d_in[3];
    const float* y    = (const float*)d_in[4];
    const float* Wih  = (const float*)d_in[5];
    const float* bih  = (const float*)d_in[6];
    const float* Whh  = (const float*)d_in[7];
    const float* bhh  = (const float*)d_in[8];
    const float* Wout = (const float*)d_in[9];
    const float* bout = (const float*)d_in[10];
    (void)in_sizes; (void)n_in;

    constexpr int SMEM_BIG  = 3 * (128 * 36 + 128 * 36) * 4;   // 110592 B
    constexpr int SMEM_STEP = 4 * (64 * 36 + 128 * 36) * 4;    // 110592 B
    cudaFuncSetAttribute(gemm_big,
                         cudaFuncAttributeMaxDynamicSharedMemorySize, SMEM_BIG);
    cudaFuncSetAttribute(steps_k,
                         cudaFuncAttributeMaxDynamicSharedMemorySize, SMEM_STEP);

    // 1) RN-round weights to tf32; reset grid barrier
    round_W_k<<<(HH * HH / 4 + 255) / 256, 256>>>(
        (const float4*)Wih, (const float4*)Whh, HH * HH / 4);

    // 2) Z = X @ W_ih^T + b_ih + b_hh   (x = n fast for L2-resident A window)
    gemm_big<<<dim3(8, 512), 256, SMEM_BIG>>>(av, bih, bhh);

    // 3) persistent recurrence (includes h0 = tanh(Z_0))
    steps_k<<<NSTEP_CTAS, 256, SMEM_STEP>>>();

    // 4) head + loss (final h in g_h[1])
    head_k<<<128, 256>>>(Wout, bout);
    loss_k<<<1, BB>>>(y, (float*)d_out, out_size);
}